// round 10
// baseline (speedup 1.0000x reference)
#include <cuda_runtime.h>

#define B_ 8
#define C_ 256
#define H_ 128
#define W_ 128
#define HW_ (H_*W_)
#define NPIX (B_*HW_)

#define CG 16            // conv channel groups
#define CPG (C_/CG)      // 16 channels per group
#define RT 16            // output rows per conv block

#define CSPLIT 4
#define CPS (C_/CSPLIT)

__device__ float2 g_part[CG * NPIX];     // conv partials (16.8 MB)
__device__ float2 g_off[NPIX];           // final clamped sample coords (px,py)

__device__ __forceinline__ unsigned long long pack2(float v) {
    unsigned long long r;
    asm("mov.b64 %0, {%1, %1};" : "=l"(r) : "f"(v));
    return r;
}
__device__ __forceinline__ void ffma2(unsigned long long& d,
                                      unsigned long long a,
                                      unsigned long long b) {
    asm("fma.rn.f32x2 %0, %1, %2, %0;" : "+l"(d) : "l"(a), "l"(b));
}
__device__ __forceinline__ void unpack2(unsigned long long v, float& lo, float& hi) {
    asm("mov.b64 {%0, %1}, %2;" : "=f"(lo), "=f"(hi) : "l"(v));
}
__device__ __forceinline__ void stcs2(float* p, float a, float b) {
    asm volatile("st.global.cs.v2.f32 [%0], {%1, %2};" :: "l"(p), "f"(a), "f"(b));
}

// ---------------------------------------------------------------------------
// Kernel 1 (r3 form): offset conv partials, f32x2 packed, shuffle halos.
// Grid: B_*(H_/RT)*CG = 1024 blocks, 128 threads.
// ---------------------------------------------------------------------------
__global__ __launch_bounds__(128) void conv_kernel(const float* __restrict__ x,
                                                   const float* __restrict__ wc) {
    const int lane = threadIdx.x & 31;
    const int wrp  = threadIdx.x >> 5;
    int bx = blockIdx.x;
    const int g  = bx & 15; bx >>= 4;
    const int hb = bx & 7;  bx >>= 3;
    const int b  = bx;
    const int h0   = hb * RT + wrp * 4;
    const int c0   = g * CPG;
    const int col0 = lane * 4;

    __shared__ float2 swp[CPG * 9];
    for (int i = threadIdx.x; i < CPG * 9; i += 128)
        swp[i] = make_float2(wc[c0 * 9 + i], wc[C_ * 9 + c0 * 9 + i]);
    __syncthreads();

    unsigned long long acc[4][4];
#pragma unroll
    for (int r = 0; r < 4; r++)
#pragma unroll
        for (int j = 0; j < 4; j++) acc[r][j] = 0ull;

    const float* xb = x + (size_t)(b * C_ + c0) * HW_;

#pragma unroll 1
    for (int c = 0; c < CPG; c++) {
        const float* xc = xb + c * HW_;
        float4 f[6];
#pragma unroll
        for (int r = 0; r < 6; r++) {
            const int hr = h0 - 1 + r;
            if (hr >= 0 && hr < H_) f[r] = *(const float4*)(xc + hr * W_ + col0);
            else                    f[r] = make_float4(0.f, 0.f, 0.f, 0.f);
        }

        float colv[6][6];
#pragma unroll
        for (int r = 0; r < 6; r++) {
            float lh = __shfl_up_sync(0xffffffffu, f[r].w, 1);
            float rh = __shfl_down_sync(0xffffffffu, f[r].x, 1);
            if (lane == 0)  lh = 0.f;
            if (lane == 31) rh = 0.f;
            colv[r][0] = lh;   colv[r][1] = f[r].x; colv[r][2] = f[r].y;
            colv[r][3] = f[r].z; colv[r][4] = f[r].w; colv[r][5] = rh;
        }

        unsigned long long wp[9];
#pragma unroll
        for (int k = 0; k < 9; k++)
            wp[k] = *(const unsigned long long*)&swp[c * 9 + k];

#pragma unroll
        for (int ri = 0; ri < 6; ri++)
#pragma unroll
            for (int ci = 0; ci < 6; ci++) {
                const unsigned long long v2 = pack2(colv[ri][ci]);
#pragma unroll
                for (int kh = 0; kh < 3; kh++) {
                    const int rr = ri - kh;
                    if (rr < 0 || rr > 3) continue;
#pragma unroll
                    for (int kw = 0; kw < 3; kw++) {
                        const int j = ci - kw;
                        if (j < 0 || j > 3) continue;
                        ffma2(acc[rr][j], wp[kh * 3 + kw], v2);
                    }
                }
            }
    }

    float2* gp = g_part + (size_t)g * NPIX + b * HW_;
#pragma unroll
    for (int rr = 0; rr < 4; rr++)
#pragma unroll
        for (int j = 0; j < 4; j++) {
            float axv, ayv;
            unpack2(acc[rr][j], axv, ayv);
            gp[(h0 + rr) * W_ + col0 + j] = make_float2(axv, ayv);
        }
}

// ---------------------------------------------------------------------------
// Kernel 1.5: merge partials + bias + base grid + clamp -> final (px,py).
// ---------------------------------------------------------------------------
__global__ __launch_bounds__(256) void reduce_kernel(const float* __restrict__ bc) {
    const int i = blockIdx.x * 256 + threadIdx.x;
    float ox = bc[0], oy = bc[1];
#pragma unroll
    for (int g = 0; g < CG; g++) {
        const float2 p = __ldg(&g_part[(size_t)g * NPIX + i]);
        ox += p.x; oy += p.y;
    }
    const int h = (i >> 7) & (H_ - 1);
    const int w = i & (W_ - 1);
    float px = (float)h + ox;
    float py = (float)w + oy;
    px = fminf(fmaxf(px, 0.f), (float)(H_ - 2));
    py = fminf(fmaxf(py, 0.f), (float)(W_ - 2));
    g_off[i] = make_float2(px, py);
}

// ---------------------------------------------------------------------------
// Kernel 2: bilinear gather, 2 column-adjacent pixels per thread.
// Block: 2 rows x 128 cols, 128 threads (thread -> row h0+(t>>6),
// cols 2*(t&63), 2*(t&63)+1). Warp load instrs span 64 consecutive columns
// -> fewer L1 wavefronts per output. Paired outputs stored as one v2.f32.
// Grid: B_*(H_/2)*CSPLIT = 2048 blocks.
// ---------------------------------------------------------------------------
__global__ __launch_bounds__(128) void sample_kernel(const float* __restrict__ x,
                                                     float* __restrict__ out) {
    const int t = threadIdx.x;
    int bx = blockIdx.x;
    const int s  = bx & (CSPLIT - 1); bx >>= 2;
    const int hp = bx & 63;           bx >>= 6;
    const int b  = bx;
    const int h  = hp * 2 + (t >> 6);
    const int w0 = (t & 63) * 2;

    const float2 pa = __ldg(&g_off[(b * H_ + h) * W_ + w0]);
    const float2 pb = __ldg(&g_off[(b * H_ + h) * W_ + w0 + 1]);

    // pixel A
    const float fxa = floorf(pa.x), fya = floorf(pa.y);
    const float dxa = pa.x - fxa,   dya = pa.y - fya;
    const float a00 = (1.f - dxa) * (1.f - dya);
    const float a01 = (1.f - dxa) * dya;
    const float a10 = dxa * (1.f - dya);
    const float a11 = dxa * dya;
    // pixel B
    const float fxb = floorf(pb.x), fyb = floorf(pb.y);
    const float dxb = pb.x - fxb,   dyb = pb.y - fyb;
    const float b00 = (1.f - dxb) * (1.f - dyb);
    const float b01 = (1.f - dxb) * dyb;
    const float b10 = dxb * (1.f - dyb);
    const float b11 = dxb * dyb;

    const int offa = (int)fxa * W_ + (int)fya;
    const int offb = (int)fxb * W_ + (int)fyb;

    const float* base = x   + ((size_t)b * C_ + s * CPS) * HW_;
    float*       op   = out + ((size_t)b * C_ + s * CPS) * HW_ + h * W_ + w0;

#pragma unroll 4
    for (int c = 0; c < CPS; c++) {
        const float* pl = base + c * HW_;
        const float* qa = pl + offa;
        const float* qb = pl + offb;
        const float va00 = __ldg(qa);
        const float va01 = __ldg(qa + 1);
        const float va10 = __ldg(qa + W_);
        const float va11 = __ldg(qa + W_ + 1);
        const float vb00 = __ldg(qb);
        const float vb01 = __ldg(qb + 1);
        const float vb10 = __ldg(qb + W_);
        const float vb11 = __ldg(qb + W_ + 1);
        const float ra = fmaf(a00, va00, fmaf(a01, va01, fmaf(a10, va10, a11 * va11)));
        const float rb = fmaf(b00, vb00, fmaf(b01, vb01, fmaf(b10, vb10, b11 * vb11)));
        stcs2(op + c * HW_, ra, rb);
    }
}

// ---------------------------------------------------------------------------
extern "C" void kernel_launch(void* const* d_in, const int* in_sizes, int n_in,
                              void* d_out, int out_size) {
    const float* x  = (const float*)d_in[0];   // [8,256,128,128]
    const float* wc = (const float*)d_in[1];   // [2,256,3,3]
    const float* bc = (const float*)d_in[2];   // [2]
    float* out = (float*)d_out;                // [8,256,128,128,1]

    conv_kernel<<<B_ * (H_ / RT) * CG, 128>>>(x, wc);
    reduce_kernel<<<NPIX / 256, 256>>>(bc);
    sample_kernel<<<B_ * (H_ / 2) * CSPLIT, 128>>>(x, out);
}

// round 11
// speedup vs baseline: 1.0156x; 1.0156x over previous
#include <cuda_runtime.h>

#define B_ 8
#define C_ 256
#define H_ 128
#define W_ 128
#define HW_ (H_*W_)
#define NPIX (B_*HW_)

#define CG 16            // conv channel groups
#define CPG (C_/CG)      // 16 channels per group
#define RT 16            // output rows per conv block

#define CSPLIT 4
#define CPS (C_/CSPLIT)

__device__ float2 g_part[CG * NPIX];     // conv partials (16.8 MB)
__device__ float2 g_off[NPIX];           // final clamped sample coords (px,py)

__device__ __forceinline__ unsigned long long pack2(float v) {
    unsigned long long r;
    asm("mov.b64 %0, {%1, %1};" : "=l"(r) : "f"(v));
    return r;
}
__device__ __forceinline__ void ffma2(unsigned long long& d,
                                      unsigned long long a,
                                      unsigned long long b) {
    asm("fma.rn.f32x2 %0, %1, %2, %0;" : "+l"(d) : "l"(a), "l"(b));
}
__device__ __forceinline__ void unpack2(unsigned long long v, float& lo, float& hi) {
    asm("mov.b64 {%0, %1}, %2;" : "=f"(lo), "=f"(hi) : "l"(v));
}
__device__ __forceinline__ void stcs2(float* p, float a, float b) {
    asm volatile("st.global.cs.v2.f32 [%0], {%1, %2};" :: "l"(p), "f"(a), "f"(b));
}

// ---------------------------------------------------------------------------
// Kernel 1 (r3 form): offset conv partials, f32x2 packed, shuffle halos.
// Grid: B_*(H_/RT)*CG = 1024 blocks, 128 threads.
// ---------------------------------------------------------------------------
__global__ __launch_bounds__(128) void conv_kernel(const float* __restrict__ x,
                                                   const float* __restrict__ wc) {
    const int lane = threadIdx.x & 31;
    const int wrp  = threadIdx.x >> 5;
    int bx = blockIdx.x;
    const int g  = bx & 15; bx >>= 4;
    const int hb = bx & 7;  bx >>= 3;
    const int b  = bx;
    const int h0   = hb * RT + wrp * 4;
    const int c0   = g * CPG;
    const int col0 = lane * 4;

    __shared__ float2 swp[CPG * 9];
    for (int i = threadIdx.x; i < CPG * 9; i += 128)
        swp[i] = make_float2(wc[c0 * 9 + i], wc[C_ * 9 + c0 * 9 + i]);
    __syncthreads();

    unsigned long long acc[4][4];
#pragma unroll
    for (int r = 0; r < 4; r++)
#pragma unroll
        for (int j = 0; j < 4; j++) acc[r][j] = 0ull;

    const float* xb = x + (size_t)(b * C_ + c0) * HW_;

#pragma unroll 1
    for (int c = 0; c < CPG; c++) {
        const float* xc = xb + c * HW_;
        float4 f[6];
#pragma unroll
        for (int r = 0; r < 6; r++) {
            const int hr = h0 - 1 + r;
            if (hr >= 0 && hr < H_) f[r] = *(const float4*)(xc + hr * W_ + col0);
            else                    f[r] = make_float4(0.f, 0.f, 0.f, 0.f);
        }

        float colv[6][6];
#pragma unroll
        for (int r = 0; r < 6; r++) {
            float lh = __shfl_up_sync(0xffffffffu, f[r].w, 1);
            float rh = __shfl_down_sync(0xffffffffu, f[r].x, 1);
            if (lane == 0)  lh = 0.f;
            if (lane == 31) rh = 0.f;
            colv[r][0] = lh;   colv[r][1] = f[r].x; colv[r][2] = f[r].y;
            colv[r][3] = f[r].z; colv[r][4] = f[r].w; colv[r][5] = rh;
        }

        unsigned long long wp[9];
#pragma unroll
        for (int k = 0; k < 9; k++)
            wp[k] = *(const unsigned long long*)&swp[c * 9 + k];

#pragma unroll
        for (int ri = 0; ri < 6; ri++)
#pragma unroll
            for (int ci = 0; ci < 6; ci++) {
                const unsigned long long v2 = pack2(colv[ri][ci]);
#pragma unroll
                for (int kh = 0; kh < 3; kh++) {
                    const int rr = ri - kh;
                    if (rr < 0 || rr > 3) continue;
#pragma unroll
                    for (int kw = 0; kw < 3; kw++) {
                        const int j = ci - kw;
                        if (j < 0 || j > 3) continue;
                        ffma2(acc[rr][j], wp[kh * 3 + kw], v2);
                    }
                }
            }
    }

    float2* gp = g_part + (size_t)g * NPIX + b * HW_;
#pragma unroll
    for (int rr = 0; rr < 4; rr++)
#pragma unroll
        for (int j = 0; j < 4; j++) {
            float axv, ayv;
            unpack2(acc[rr][j], axv, ayv);
            gp[(h0 + rr) * W_ + col0 + j] = make_float2(axv, ayv);
        }
}

// ---------------------------------------------------------------------------
// Kernel 1.5: merge partials + bias + base grid + clamp -> final (px,py).
// ---------------------------------------------------------------------------
__global__ __launch_bounds__(256) void reduce_kernel(const float* __restrict__ bc) {
    const int i = blockIdx.x * 256 + threadIdx.x;
    float ox = bc[0], oy = bc[1];
#pragma unroll
    for (int g = 0; g < CG; g++) {
        const float2 p = __ldg(&g_part[(size_t)g * NPIX + i]);
        ox += p.x; oy += p.y;
    }
    const int h = (i >> 7) & (H_ - 1);
    const int w = i & (W_ - 1);
    float px = (float)h + ox;
    float py = (float)w + oy;
    px = fminf(fmaxf(px, 0.f), (float)(H_ - 2));
    py = fminf(fmaxf(py, 0.f), (float)(W_ - 2));
    g_off[i] = make_float2(px, py);
}

// ---------------------------------------------------------------------------
// Kernel 2: bilinear gather, 2 column-adjacent pixels per thread.
// Block: 2 rows x 128 cols, 128 threads (thread -> row h0+(t>>6),
// cols 2*(t&63), 2*(t&63)+1). Warp load instrs span 64 consecutive columns
// -> fewer L1 wavefronts per output. Paired outputs stored as one v2.f32.
// Grid: B_*(H_/2)*CSPLIT = 2048 blocks.
// ---------------------------------------------------------------------------
__global__ __launch_bounds__(128) void sample_kernel(const float* __restrict__ x,
                                                     float* __restrict__ out) {
    const int t = threadIdx.x;
    int bx = blockIdx.x;
    const int s  = bx & (CSPLIT - 1); bx >>= 2;
    const int hp = bx & 63;           bx >>= 6;
    const int b  = bx;
    const int h  = hp * 2 + (t >> 6);
    const int w0 = (t & 63) * 2;

    const float2 pa = __ldg(&g_off[(b * H_ + h) * W_ + w0]);
    const float2 pb = __ldg(&g_off[(b * H_ + h) * W_ + w0 + 1]);

    // pixel A
    const float fxa = floorf(pa.x), fya = floorf(pa.y);
    const float dxa = pa.x - fxa,   dya = pa.y - fya;
    const float a00 = (1.f - dxa) * (1.f - dya);
    const float a01 = (1.f - dxa) * dya;
    const float a10 = dxa * (1.f - dya);
    const float a11 = dxa * dya;
    // pixel B
    const float fxb = floorf(pb.x), fyb = floorf(pb.y);
    const float dxb = pb.x - fxb,   dyb = pb.y - fyb;
    const float b00 = (1.f - dxb) * (1.f - dyb);
    const float b01 = (1.f - dxb) * dyb;
    const float b10 = dxb * (1.f - dyb);
    const float b11 = dxb * dyb;

    const int offa = (int)fxa * W_ + (int)fya;
    const int offb = (int)fxb * W_ + (int)fyb;

    const float* base = x   + ((size_t)b * C_ + s * CPS) * HW_;
    float*       op   = out + ((size_t)b * C_ + s * CPS) * HW_ + h * W_ + w0;

#pragma unroll 4
    for (int c = 0; c < CPS; c++) {
        const float* pl = base + c * HW_;
        const float* qa = pl + offa;
        const float* qb = pl + offb;
        const float va00 = __ldg(qa);
        const float va01 = __ldg(qa + 1);
        const float va10 = __ldg(qa + W_);
        const float va11 = __ldg(qa + W_ + 1);
        const float vb00 = __ldg(qb);
        const float vb01 = __ldg(qb + 1);
        const float vb10 = __ldg(qb + W_);
        const float vb11 = __ldg(qb + W_ + 1);
        const float ra = fmaf(a00, va00, fmaf(a01, va01, fmaf(a10, va10, a11 * va11)));
        const float rb = fmaf(b00, vb00, fmaf(b01, vb01, fmaf(b10, vb10, b11 * vb11)));
        stcs2(op + c * HW_, ra, rb);
    }
}

// ---------------------------------------------------------------------------
extern "C" void kernel_launch(void* const* d_in, const int* in_sizes, int n_in,
                              void* d_out, int out_size) {
    const float* x  = (const float*)d_in[0];   // [8,256,128,128]
    const float* wc = (const float*)d_in[1];   // [2,256,3,3]
    const float* bc = (const float*)d_in[2];   // [2]
    float* out = (float*)d_out;                // [8,256,128,128,1]

    conv_kernel<<<B_ * (H_ / RT) * CG, 128>>>(x, wc);
    reduce_kernel<<<NPIX / 256, 256>>>(bc);
    sample_kernel<<<B_ * (H_ / 2) * CSPLIT, 128>>>(x, out);
}